// round 1
// baseline (speedup 1.0000x reference)
#include <cuda_runtime.h>
#include <cuda_bf16.h>
#include <math.h>

// Problem constants
#define TOK   16384      // B*S tokens
#define DIM   1024       // model dim
#define DFF   4096       // ffn dim
#define NEXP  8          // experts
#define CAP   3277       // ceil(T*1.6/8)
#define TM    128        // GEMM row tile
#define PADMAX (TOK + NEXP*TM)          // 17408 max padded rows
#define MAXROWTILES (PADMAX/TM)         // 136

// ---------------- scratch (device globals; no allocations allowed) -------
__device__ unsigned char g_selmask[TOK];           // bit e set if e in top-2
__device__ unsigned char g_kept[NEXP * TOK];       // kept-by-expert flag
__device__ signed char   g_final[TOK];             // final (winning) expert, -1 none
__device__ int g_cnt[NEXP];
__device__ int g_fill[NEXP];
__device__ int g_off[NEXP + 1];                    // padded segment offsets
__device__ int g_perm[PADMAX];                     // padded row -> token id (TOK = pad)
__device__ float g_H[(size_t)PADMAX * DFF];        // gelu intermediate (~285MB)

// ---------------- init ---------------------------------------------------
__global__ void init_kernel() {
    int i = threadIdx.x;
    if (i < NEXP) { g_cnt[i] = 0; g_fill[i] = 0; }
}

// ---------------- router: logits + noise, top-2 --------------------------
__global__ __launch_bounds__(128) void router_kernel(
    const float* __restrict__ x, const float* __restrict__ noise,
    const float* __restrict__ rw, const float* __restrict__ rb)
{
    int t = blockIdx.x;
    const float* xr = x + (size_t)t * DIM;
    float acc[NEXP];
#pragma unroll
    for (int e = 0; e < NEXP; e++) acc[e] = 0.f;
    for (int i = threadIdx.x; i < DIM; i += 128) {
        float xv = xr[i];
#pragma unroll
        for (int e = 0; e < NEXP; e++) acc[e] += xv * rw[e * DIM + i];
    }
    __shared__ float red[NEXP][128];
#pragma unroll
    for (int e = 0; e < NEXP; e++) red[e][threadIdx.x] = acc[e];
    __syncthreads();
    for (int s = 64; s > 0; s >>= 1) {
        if (threadIdx.x < s) {
#pragma unroll
            for (int e = 0; e < NEXP; e++)
                red[e][threadIdx.x] += red[e][threadIdx.x + s];
        }
        __syncthreads();
    }
    if (threadIdx.x == 0) {
        float lg[NEXP];
#pragma unroll
        for (int e = 0; e < NEXP; e++)
            lg[e] = red[e][0] + rb[e] + noise[t * NEXP + e] * 0.02f;
        int e1 = 0;
#pragma unroll
        for (int e = 1; e < NEXP; e++) if (lg[e] > lg[e1]) e1 = e;
        int e2 = -1;
#pragma unroll
        for (int e = 0; e < NEXP; e++) {
            if (e == e1) continue;
            if (e2 < 0 || lg[e] > lg[e2]) e2 = e;
        }
        g_selmask[t] = (unsigned char)((1 << e1) | (1 << e2));
    }
}

// ---------------- per-expert rank scan (capacity filter) ------------------
__global__ __launch_bounds__(256) void rank_kernel()
{
    int e = blockIdx.x;
    int tid = threadIdx.x;
    __shared__ int sc[256];
    __shared__ int carry;
    if (tid == 0) carry = 0;
    __syncthreads();
    for (int base = 0; base < TOK; base += 256) {
        int t = base + tid;
        int m = (g_selmask[t] >> e) & 1;
        sc[tid] = m;
        __syncthreads();
        for (int s = 1; s < 256; s <<= 1) {
            int add = (tid >= s) ? sc[tid - s] : 0;
            __syncthreads();
            sc[tid] += add;
            __syncthreads();
        }
        int incl = sc[tid];
        int rank = carry + incl - m;   // exclusive rank in token order
        g_kept[e * TOK + t] = (unsigned char)(m && rank < CAP);
        __syncthreads();
        if (tid == 255) carry += incl;
        __syncthreads();
    }
}

// ---------------- final expert per token + counts -------------------------
__global__ __launch_bounds__(256) void finalize_kernel()
{
    int t = blockIdx.x * 256 + threadIdx.x;
    if (t >= TOK) return;
    unsigned char mask = g_selmask[t];
    int f = -1;
#pragma unroll
    for (int e = NEXP - 1; e >= 0; e--) {
        if (((mask >> e) & 1) && g_kept[e * TOK + t]) { f = e; break; }
    }
    g_final[t] = (signed char)f;
    if (f >= 0) atomicAdd(&g_cnt[f], 1);
}

__global__ void offsets_kernel()
{
    if (threadIdx.x == 0 && blockIdx.x == 0) {
        int o = 0;
        g_off[0] = 0;
        for (int e = 0; e < NEXP; e++) {
            o += ((g_cnt[e] + TM - 1) / TM) * TM;
            g_off[e + 1] = o;
        }
    }
}

__global__ __launch_bounds__(256) void perminit_kernel()
{
    int i = blockIdx.x * 256 + threadIdx.x;
    if (i < PADMAX) g_perm[i] = TOK;   // sentinel (pad row)
}

__global__ __launch_bounds__(256) void place_kernel()
{
    int t = blockIdx.x * 256 + threadIdx.x;
    if (t >= TOK) return;
    int f = g_final[t];
    if (f >= 0) {
        int pos = g_off[f] + atomicAdd(&g_fill[f], 1);
        g_perm[pos] = t;
    }
}

// ---------------- zero the output (dropped tokens stay 0) -----------------
__global__ __launch_bounds__(256) void zero_out_kernel(float* __restrict__ out)
{
    size_t n4 = (size_t)TOK * DIM / 4;
    float4 z = make_float4(0.f, 0.f, 0.f, 0.f);
    for (size_t i = blockIdx.x * 256 + threadIdx.x; i < n4;
         i += (size_t)gridDim.x * 256)
        reinterpret_cast<float4*>(out)[i] = z;
}

// ---------------- FFN pass 1: H = gelu(Xg @ W1 + b1) ----------------------
__device__ __forceinline__ float gelu_exact(float v) {
    return 0.5f * v * (1.0f + erff(v * 0.70710678118654752f));
}

__global__ __launch_bounds__(256) void ffn1_kernel(
    const float* __restrict__ x, const float* __restrict__ w1,
    const float* __restrict__ b1)
{
    int row0 = blockIdx.y * TM;
    if (row0 >= g_off[NEXP]) return;
    int e = 0;
#pragma unroll
    for (int i = 0; i < NEXP; i++) if (row0 >= g_off[i + 1]) e = i + 1;

    int n0 = blockIdx.x * 128;
    __shared__ float As[16][128];
    __shared__ float Bs[16][132];
    __shared__ int stok[128];
    int tid = threadIdx.x;
    if (tid < 128) stok[tid] = g_perm[row0 + tid];
    __syncthreads();

    const float* w1e = w1 + (size_t)e * DIM * DFF;
    int tx = tid & 15, ty = tid >> 4;
    float acc[8][8];
#pragma unroll
    for (int i = 0; i < 8; i++)
#pragma unroll
        for (int j = 0; j < 8; j++) acc[i][j] = 0.f;

    for (int k0 = 0; k0 < DIM; k0 += 16) {
        // A: gather 128 token rows x 16 k
#pragma unroll
        for (int q = 0; q < 2; q++) {
            int v = tid * 2 + q;
            int row = v >> 2, kq = (v & 3) * 4;
            int tok = stok[row];
            float4 av = make_float4(0.f, 0.f, 0.f, 0.f);
            if (tok < TOK)
                av = *reinterpret_cast<const float4*>(x + (size_t)tok * DIM + k0 + kq);
            As[kq + 0][row] = av.x; As[kq + 1][row] = av.y;
            As[kq + 2][row] = av.z; As[kq + 3][row] = av.w;
        }
        // B: 16 k x 128 n
#pragma unroll
        for (int q = 0; q < 2; q++) {
            int v = tid * 2 + q;
            int r = v >> 5, c = (v & 31) * 4;
            float4 bv = *reinterpret_cast<const float4*>(
                w1e + (size_t)(k0 + r) * DFF + n0 + c);
            Bs[r][c + 0] = bv.x; Bs[r][c + 1] = bv.y;
            Bs[r][c + 2] = bv.z; Bs[r][c + 3] = bv.w;
        }
        __syncthreads();
#pragma unroll
        for (int kk = 0; kk < 16; kk++) {
            float a[8], b[8];
#pragma unroll
            for (int i = 0; i < 8; i++) a[i] = As[kk][ty * 8 + i];
#pragma unroll
            for (int j = 0; j < 8; j++) b[j] = Bs[kk][tx * 8 + j];
#pragma unroll
            for (int i = 0; i < 8; i++)
#pragma unroll
                for (int j = 0; j < 8; j++) acc[i][j] += a[i] * b[j];
        }
        __syncthreads();
    }
    // epilogue: +b1, gelu, store to H at padded row
#pragma unroll
    for (int i = 0; i < 8; i++) {
        size_t hrow = (size_t)(row0 + ty * 8 + i) * DFF;
#pragma unroll
        for (int jq = 0; jq < 2; jq++) {
            int n = n0 + tx * 8 + jq * 4;
            float4 o;
            o.x = gelu_exact(acc[i][jq * 4 + 0] + b1[e * DFF + n + 0]);
            o.y = gelu_exact(acc[i][jq * 4 + 1] + b1[e * DFF + n + 1]);
            o.z = gelu_exact(acc[i][jq * 4 + 2] + b1[e * DFF + n + 2]);
            o.w = gelu_exact(acc[i][jq * 4 + 3] + b1[e * DFF + n + 3]);
            *reinterpret_cast<float4*>(&g_H[hrow + n]) = o;
        }
    }
}

// ---------------- FFN pass 2: out = H @ W2 + b2 (scatter) -----------------
__global__ __launch_bounds__(256) void ffn2_kernel(
    const float* __restrict__ w2, const float* __restrict__ b2,
    float* __restrict__ out)
{
    int row0 = blockIdx.y * TM;
    if (row0 >= g_off[NEXP]) return;
    int e = 0;
#pragma unroll
    for (int i = 0; i < NEXP; i++) if (row0 >= g_off[i + 1]) e = i + 1;

    int n0 = blockIdx.x * 128;
    __shared__ float As[16][128];
    __shared__ float Bs[16][132];
    __shared__ int stok[128];
    int tid = threadIdx.x;
    if (tid < 128) stok[tid] = g_perm[row0 + tid];
    __syncthreads();

    const float* w2e = w2 + (size_t)e * DFF * DIM;
    int tx = tid & 15, ty = tid >> 4;
    float acc[8][8];
#pragma unroll
    for (int i = 0; i < 8; i++)
#pragma unroll
        for (int j = 0; j < 8; j++) acc[i][j] = 0.f;

    for (int k0 = 0; k0 < DFF; k0 += 16) {
#pragma unroll
        for (int q = 0; q < 2; q++) {
            int v = tid * 2 + q;
            int row = v >> 2, kq = (v & 3) * 4;
            float4 av = *reinterpret_cast<const float4*>(
                &g_H[(size_t)(row0 + row) * DFF + k0 + kq]);
            As[kq + 0][row] = av.x; As[kq + 1][row] = av.y;
            As[kq + 2][row] = av.z; As[kq + 3][row] = av.w;
        }
#pragma unroll
        for (int q = 0; q < 2; q++) {
            int v = tid * 2 + q;
            int r = v >> 5, c = (v & 31) * 4;
            float4 bv = *reinterpret_cast<const float4*>(
                w2e + (size_t)(k0 + r) * DIM + n0 + c);
            Bs[r][c + 0] = bv.x; Bs[r][c + 1] = bv.y;
            Bs[r][c + 2] = bv.z; Bs[r][c + 3] = bv.w;
        }
        __syncthreads();
#pragma unroll
        for (int kk = 0; kk < 16; kk++) {
            float a[8], b[8];
#pragma unroll
            for (int i = 0; i < 8; i++) a[i] = As[kk][ty * 8 + i];
#pragma unroll
            for (int j = 0; j < 8; j++) b[j] = Bs[kk][tx * 8 + j];
#pragma unroll
            for (int i = 0; i < 8; i++)
#pragma unroll
                for (int j = 0; j < 8; j++) acc[i][j] += a[i] * b[j];
        }
        __syncthreads();
    }
#pragma unroll
    for (int i = 0; i < 8; i++) {
        int tok = stok[ty * 8 + i];
        if (tok >= TOK) continue;
        size_t orow = (size_t)tok * DIM;
#pragma unroll
        for (int jq = 0; jq < 2; jq++) {
            int n = n0 + tx * 8 + jq * 4;
            float4 o;
            o.x = acc[i][jq * 4 + 0] + b2[e * DIM + n + 0];
            o.y = acc[i][jq * 4 + 1] + b2[e * DIM + n + 1];
            o.z = acc[i][jq * 4 + 2] + b2[e * DIM + n + 2];
            o.w = acc[i][jq * 4 + 3] + b2[e * DIM + n + 3];
            *reinterpret_cast<float4*>(out + orow + n) = o;
        }
    }
}

// ---------------- launch --------------------------------------------------
extern "C" void kernel_launch(void* const* d_in, const int* in_sizes, int n_in,
                              void* d_out, int out_size)
{
    const float* x     = (const float*)d_in[0];
    const float* noise = (const float*)d_in[1];
    const float* rw    = (const float*)d_in[2];
    const float* rb    = (const float*)d_in[3];
    const float* w1    = (const float*)d_in[4];
    const float* b1    = (const float*)d_in[5];
    const float* w2    = (const float*)d_in[6];
    const float* b2    = (const float*)d_in[7];
    float* out = (float*)d_out;

    init_kernel<<<1, 32>>>();
    router_kernel<<<TOK, 128>>>(x, noise, rw, rb);
    rank_kernel<<<NEXP, 256>>>();
    finalize_kernel<<<TOK / 256, 256>>>();
    offsets_kernel<<<1, 32>>>();
    perminit_kernel<<<(PADMAX + 255) / 256, 256>>>();
    place_kernel<<<TOK / 256, 256>>>();
    zero_out_kernel<<<2048, 256>>>(out);
    ffn1_kernel<<<dim3(DFF / 128, MAXROWTILES), 256>>>(x, w1, b1);
    ffn2_kernel<<<dim3(DIM / 128, MAXROWTILES), 256>>>(w2, b2, out);
}

// round 3
// speedup vs baseline: 2.5659x; 2.5659x over previous
#include <cuda_runtime.h>
#include <cuda_bf16.h>
#include <math.h>
#include <stdint.h>

// ---------------- problem constants ----------------
#define TOK   16384
#define DIM   1024
#define DFF   4096
#define NEXP  8
#define CAP   3277
#define TM    128
#define PADMAX (TOK + NEXP*TM)          // 17408
#define MAXROWTILES (PADMAX/TM)         // 136
#define KC    64                         // K chunk (bf16 elems)
#define STAGE 65536                      // Ah16K Al16K Bh16K Bl16K
#define SMEM_REQ (2*STAGE + 1024)

// ---------------- device scratch ----------------
__device__ unsigned char g_selmask[TOK];
__device__ unsigned char g_kept[NEXP * TOK];
__device__ signed char   g_final[TOK];
__device__ int g_cnt[NEXP];
__device__ int g_fill[NEXP];
__device__ int g_off[NEXP + 1];
__device__ int g_perm[PADMAX];
__device__ __nv_bfloat16 g_Agh[(size_t)PADMAX * DIM];
__device__ __nv_bfloat16 g_Agl[(size_t)PADMAX * DIM];
__device__ __nv_bfloat16 g_Hh[(size_t)PADMAX * DFF];
__device__ __nv_bfloat16 g_Hl[(size_t)PADMAX * DFF];
__device__ __nv_bfloat16 g_W1h[(size_t)NEXP * DFF * DIM];
__device__ __nv_bfloat16 g_W1l[(size_t)NEXP * DFF * DIM];
__device__ __nv_bfloat16 g_W2h[(size_t)NEXP * DIM * DFF];
__device__ __nv_bfloat16 g_W2l[(size_t)NEXP * DIM * DFF];

// ---------------- helpers ----------------
__device__ __forceinline__ uint32_t smem_u32(const void* p) {
    return (uint32_t)__cvta_generic_to_shared(p);
}
#define SWZ128(o) ((o) ^ (((o) >> 3) & 0x70))

#define CP16(dst, src) \
    asm volatile("cp.async.cg.shared.global [%0], [%1], 16;" :: "r"(dst), "l"(src) : "memory")
#define CP_COMMIT() asm volatile("cp.async.commit_group;" ::: "memory")
#define CP_WAIT1()  asm volatile("cp.async.wait_group 1;" ::: "memory")
#define CP_WAIT0()  asm volatile("cp.async.wait_group 0;" ::: "memory")

__device__ __forceinline__ void ldsm4(uint32_t& r0, uint32_t& r1, uint32_t& r2,
                                      uint32_t& r3, uint32_t addr) {
    asm volatile("ldmatrix.sync.aligned.m8n8.x4.shared.b16 {%0,%1,%2,%3}, [%4];"
                 : "=r"(r0), "=r"(r1), "=r"(r2), "=r"(r3) : "r"(addr));
}

__device__ __forceinline__ void mma16816(float* c, const uint32_t* a,
                                         uint32_t b0, uint32_t b1) {
    asm volatile(
        "mma.sync.aligned.m16n8k16.row.col.f32.bf16.bf16.f32 "
        "{%0,%1,%2,%3}, {%4,%5,%6,%7}, {%8,%9}, {%0,%1,%2,%3};"
        : "+f"(c[0]), "+f"(c[1]), "+f"(c[2]), "+f"(c[3])
        : "r"(a[0]), "r"(a[1]), "r"(a[2]), "r"(a[3]), "r"(b0), "r"(b1));
}

__device__ __forceinline__ float gelu_exact(float v) {
    return 0.5f * v * (1.0f + erff(v * 0.70710678118654752f));
}

// ---------------- routing kernels (unchanged, proven) ----------------
__global__ void init_kernel() {
    int i = threadIdx.x;
    if (i < NEXP) { g_cnt[i] = 0; g_fill[i] = 0; }
}

__global__ __launch_bounds__(128) void router_kernel(
    const float* __restrict__ x, const float* __restrict__ noise,
    const float* __restrict__ rw, const float* __restrict__ rb)
{
    int t = blockIdx.x;
    const float* xr = x + (size_t)t * DIM;
    float acc[NEXP];
#pragma unroll
    for (int e = 0; e < NEXP; e++) acc[e] = 0.f;
    for (int i = threadIdx.x; i < DIM; i += 128) {
        float xv = xr[i];
#pragma unroll
        for (int e = 0; e < NEXP; e++) acc[e] += xv * rw[e * DIM + i];
    }
    __shared__ float red[NEXP][128];
#pragma unroll
    for (int e = 0; e < NEXP; e++) red[e][threadIdx.x] = acc[e];
    __syncthreads();
    for (int s = 64; s > 0; s >>= 1) {
        if (threadIdx.x < s) {
#pragma unroll
            for (int e = 0; e < NEXP; e++)
                red[e][threadIdx.x] += red[e][threadIdx.x + s];
        }
        __syncthreads();
    }
    if (threadIdx.x == 0) {
        float lg[NEXP];
#pragma unroll
        for (int e = 0; e < NEXP; e++)
            lg[e] = red[e][0] + rb[e] + noise[t * NEXP + e] * 0.02f;
        int e1 = 0;
#pragma unroll
        for (int e = 1; e < NEXP; e++) if (lg[e] > lg[e1]) e1 = e;
        int e2 = -1;
#pragma unroll
        for (int e = 0; e < NEXP; e++) {
            if (e == e1) continue;
            if (e2 < 0 || lg[e] > lg[e2]) e2 = e;
        }
        g_selmask[t] = (unsigned char)((1 << e1) | (1 << e2));
    }
}

__global__ __launch_bounds__(256) void rank_kernel()
{
    int e = blockIdx.x;
    int tid = threadIdx.x;
    __shared__ int sc[256];
    __shared__ int carry;
    if (tid == 0) carry = 0;
    __syncthreads();
    for (int base = 0; base < TOK; base += 256) {
        int t = base + tid;
        int m = (g_selmask[t] >> e) & 1;
        sc[tid] = m;
        __syncthreads();
        for (int s = 1; s < 256; s <<= 1) {
            int add = (tid >= s) ? sc[tid - s] : 0;
            __syncthreads();
            sc[tid] += add;
            __syncthreads();
        }
        int incl = sc[tid];
        int rank = carry + incl - m;
        g_kept[e * TOK + t] = (unsigned char)(m && rank < CAP);
        __syncthreads();
        if (tid == 255) carry += incl;
        __syncthreads();
    }
}

__global__ __launch_bounds__(256) void finalize_kernel()
{
    int t = blockIdx.x * 256 + threadIdx.x;
    if (t >= TOK) return;
    unsigned char mask = g_selmask[t];
    int f = -1;
#pragma unroll
    for (int e = NEXP - 1; e >= 0; e--) {
        if (((mask >> e) & 1) && g_kept[e * TOK + t]) { f = e; break; }
    }
    g_final[t] = (signed char)f;
    if (f >= 0) atomicAdd(&g_cnt[f], 1);
}

__global__ void offsets_kernel()
{
    if (threadIdx.x == 0 && blockIdx.x == 0) {
        int o = 0;
        g_off[0] = 0;
        for (int e = 0; e < NEXP; e++) {
            o += ((g_cnt[e] + TM - 1) / TM) * TM;
            g_off[e + 1] = o;
        }
    }
}

__global__ __launch_bounds__(256) void perminit_kernel()
{
    int i = blockIdx.x * 256 + threadIdx.x;
    if (i < PADMAX) g_perm[i] = TOK;
}

__global__ __launch_bounds__(256) void place_kernel()
{
    int t = blockIdx.x * 256 + threadIdx.x;
    if (t >= TOK) return;
    int f = g_final[t];
    if (f >= 0) {
        int pos = g_off[f] + atomicAdd(&g_fill[f], 1);
        g_perm[pos] = t;
    }
}

__global__ __launch_bounds__(256) void zero_out_kernel(float* __restrict__ out)
{
    size_t n4 = (size_t)TOK * DIM / 4;
    float4 z = make_float4(0.f, 0.f, 0.f, 0.f);
    for (size_t i = blockIdx.x * 256 + threadIdx.x; i < n4;
         i += (size_t)gridDim.x * 256)
        reinterpret_cast<float4*>(out)[i] = z;
}

// ---------------- conversion kernels ----------------
// Transpose + bf16 split: src fp32 [E, R, C] -> dst bf16 [E, C, R] hi/lo
__global__ __launch_bounds__(256) void transcvt_kernel(
    const float* __restrict__ src, __nv_bfloat16* __restrict__ dh,
    __nv_bfloat16* __restrict__ dl, int R, int C)
{
    __shared__ float t[32][33];
    int e = blockIdx.z;
    const float* s = src + (size_t)e * R * C;
    int c0 = blockIdx.x * 32, r0 = blockIdx.y * 32;
    int tx = threadIdx.x, ty = threadIdx.y;
#pragma unroll
    for (int i = 0; i < 4; i++)
        t[ty + i * 8][tx] = s[(size_t)(r0 + ty + i * 8) * C + c0 + tx];
    __syncthreads();
#pragma unroll
    for (int i = 0; i < 4; i++) {
        int orow = c0 + ty + i * 8;
        int ocol = r0 + tx;
        float v = t[tx][ty + i * 8];
        __nv_bfloat16 h = __float2bfloat16(v);
        __nv_bfloat16 l = __float2bfloat16(v - __bfloat162float(h));
        size_t di = ((size_t)e * C + orow) * R + ocol;
        dh[di] = h; dl[di] = l;
    }
}

__global__ __launch_bounds__(256) void gather_kernel(const float* __restrict__ x)
{
    int pr = blockIdx.x;
    int tok = g_perm[pr];
    int tid = threadIdx.x;
    float4 v = make_float4(0.f, 0.f, 0.f, 0.f);
    if (tok < TOK)
        v = reinterpret_cast<const float4*>(x + (size_t)tok * DIM)[tid];
    __nv_bfloat16 h[4], l[4];
    float vv[4] = {v.x, v.y, v.z, v.w};
#pragma unroll
    for (int i = 0; i < 4; i++) {
        h[i] = __float2bfloat16(vv[i]);
        l[i] = __float2bfloat16(vv[i] - __bfloat162float(h[i]));
    }
    size_t base = (size_t)pr * DIM;
    reinterpret_cast<uint2*>(g_Agh + base)[tid] = *reinterpret_cast<uint2*>(h);
    reinterpret_cast<uint2*>(g_Agl + base)[tid] = *reinterpret_cast<uint2*>(l);
}

// ---------------- HMMA GEMM (both FFN passes) ----------------
// D[128x128 tile] = A[128 x K] * B^T, B: [N_TOT x K] row-major (k contiguous).
// 3-term bf16 split: Ah*Bh + Ah*Bl + Al*Bh, fp32 accum.
// mode 1: +b1 -> gelu -> hi/lo split -> g_Hh/g_Hl
// mode 2: +b2 -> scatter fp32 rows to out[token]
__global__ __launch_bounds__(256, 1) void gemm_kernel(
    const __nv_bfloat16* __restrict__ Ah, const __nv_bfloat16* __restrict__ Al,
    const __nv_bfloat16* __restrict__ Bh, const __nv_bfloat16* __restrict__ Bl,
    const float* __restrict__ bias, float* __restrict__ out,
    int K_TOT, int N_TOT, int mode)
{
    int row0 = blockIdx.y * TM;
    if (row0 >= g_off[NEXP]) return;
    int e = 0;
#pragma unroll
    for (int i = 0; i < NEXP; i++) if (row0 >= g_off[i + 1]) e = i + 1;
    int n0 = blockIdx.x * 128;

    extern __shared__ __align__(1024) char smem_raw[];
    uint32_t sb = (smem_u32(smem_raw) + 1023) & ~1023u;

    int tid = threadIdx.x;
    int lane = tid & 31;
    int wid = tid >> 5;
    int wm = wid & 3;          // warp m position (4 x 32 rows)
    int wn = wid >> 2;         // warp n position (2 x 64 cols)
    int lrow = (lane & 7) + ((lane >> 3) & 1) * 8;  // ldmatrix row within 16
    int lkh  = (lane >> 4) * 8;                      // ldmatrix k-half (elems)

    const size_t eN = (size_t)e * N_TOT;
    const int C = K_TOT >> 6;

    // stage fill: 4096 x 16B cp.async (A hi/lo + B hi/lo, 128x64 bf16 each)
    auto fill_stage = [&](int s, int c) {
        uint32_t st = sb + s * STAGE;
        int k0 = c * KC;
#pragma unroll
        for (int j = 0; j < 4; j++) {
            int u = tid + j * 256;
            int row = u >> 3, kp = u & 7;
            uint32_t so = SWZ128(row * 128 + kp * 16);
            size_t gi = (size_t)(row0 + row) * K_TOT + k0 + kp * 8;
            CP16(st + so,         (const char*)(Ah + gi));
            CP16(st + 16384 + so, (const char*)(Al + gi));
            size_t gb = (eN + n0 + row) * K_TOT + k0 + kp * 8;
            CP16(st + 32768 + so, (const char*)(Bh + gb));
            CP16(st + 49152 + so, (const char*)(Bl + gb));
        }
    };

    float acc[2][8][4];
#pragma unroll
    for (int mt = 0; mt < 2; mt++)
#pragma unroll
        for (int nf = 0; nf < 8; nf++)
#pragma unroll
            for (int q = 0; q < 4; q++) acc[mt][nf][q] = 0.f;

    fill_stage(0, 0); CP_COMMIT();
    fill_stage(1, 1); CP_COMMIT();

    for (int c = 0; c < C; ++c) {
        int s = c & 1;
        CP_WAIT1();
        __syncthreads();
        uint32_t st = sb + s * STAGE;
#pragma unroll
        for (int ks = 0; ks < 4; ks++) {
            int kbyte = ks * 32 + lkh * 2;
            uint32_t ah[2][4], al[2][4], bh[4][4], bl[4][4];
#pragma unroll
            for (int mt = 0; mt < 2; mt++) {
                uint32_t off = SWZ128((wm * 32 + mt * 16 + lrow) * 128 + kbyte);
                ldsm4(ah[mt][0], ah[mt][1], ah[mt][2], ah[mt][3], st + off);
                ldsm4(al[mt][0], al[mt][1], al[mt][2], al[mt][3], st + 16384 + off);
            }
#pragma unroll
            for (int nt = 0; nt < 4; nt++) {
                uint32_t off = SWZ128((wn * 64 + nt * 16 + lrow) * 128 + kbyte);
                ldsm4(bh[nt][0], bh[nt][1], bh[nt][2], bh[nt][3], st + 32768 + off);
                ldsm4(bl[nt][0], bl[nt][1], bl[nt][2], bl[nt][3], st + 49152 + off);
            }
            // product 0: Ah*Bh
#pragma unroll
            for (int mt = 0; mt < 2; mt++)
#pragma unroll
                for (int nt = 0; nt < 4; nt++) {
                    mma16816(acc[mt][nt * 2],     ah[mt], bh[nt][0], bh[nt][2]);
                    mma16816(acc[mt][nt * 2 + 1], ah[mt], bh[nt][1], bh[nt][3]);
                }
            // product 1: Ah*Bl
#pragma unroll
            for (int mt = 0; mt < 2; mt++)
#pragma unroll
                for (int nt = 0; nt < 4; nt++) {
                    mma16816(acc[mt][nt * 2],     ah[mt], bl[nt][0], bl[nt][2]);
                    mma16816(acc[mt][nt * 2 + 1], ah[mt], bl[nt][1], bl[nt][3]);
                }
            // product 2: Al*Bh
#pragma unroll
            for (int mt = 0; mt < 2; mt++)
#pragma unroll
                for (int nt = 0; nt < 4; nt++) {
                    mma16816(acc[mt][nt * 2],     al[mt], bh[nt][0], bh[nt][2]);
                    mma16816(acc[mt][nt * 2 + 1], al[mt], bh[nt][1], bh[nt][3]);
                }
        }
        __syncthreads();
        if (c + 2 < C) { fill_stage(s, c + 2); CP_COMMIT(); }
    }
    CP_WAIT0();

    // ---- epilogue ----
    int colb = (lane & 3) * 2;           // col pair within n8 frag
#pragma unroll
    for (int mt = 0; mt < 2; mt++) {
        int rA = row0 + wm * 32 + mt * 16 + (lane >> 2);
        int rB = rA + 8;
        int tokA = 0, tokB = 0;
        if (mode == 2) { tokA = g_perm[rA]; tokB = g_perm[rB]; }
#pragma unroll
        for (int nf = 0; nf < 8; nf++) {
            int col = n0 + wn * 64 + nf * 8 + colb;
            float bi0 = bias[(size_t)e * N_TOT + col];
            float bi1 = bias[(size_t)e * N_TOT + col + 1];
            float vA0 = acc[mt][nf][0] + bi0, vA1 = acc[mt][nf][1] + bi1;
            float vB0 = acc[mt][nf][2] + bi0, vB1 = acc[mt][nf][3] + bi1;
            if (mode == 1) {
                float hA0 = gelu_exact(vA0), hA1 = gelu_exact(vA1);
                float hB0 = gelu_exact(vB0), hB1 = gelu_exact(vB1);
                __nv_bfloat162 hh, hl;
                hh.x = __float2bfloat16(hA0);
                hh.y = __float2bfloat16(hA1);
                hl.x = __float2bfloat16(hA0 - __bfloat162float(hh.x));
                hl.y = __float2bfloat16(hA1 - __bfloat162float(hh.y));
                *reinterpret_cast<__nv_bfloat162*>(g_Hh + (size_t)rA * DFF + col) = hh;
                *reinterpret_cast<__nv_bfloat162*>(g_Hl + (size_t)rA * DFF + col) = hl;
                hh.x = __float2bfloat16(hB0);
                hh.y = __float2bfloat16(hB1);
                hl.x = __float2bfloat16(hB0 - __bfloat162float(hh.x));
                hl.y = __float2bfloat16(hB1 - __bfloat162float(hh.y));
                *reinterpret_cast<__nv_bfloat162*>(g_Hh + (size_t)rB * DFF + col) = hh;
                *reinterpret_cast<__nv_bfloat162*>(g_Hl + (size_t)rB * DFF + col) = hl;
            } else {
                if (tokA < TOK) {
                    float2 o = make_float2(vA0, vA1);
                    *reinterpret_cast<float2*>(out + (size_t)tokA * DIM + col) = o;
                }
                if (tokB < TOK) {
                    float2 o = make_float2(vB0, vB1);
                    *reinterpret_cast<float2*>(out + (size_t)tokB * DIM + col) = o;
                }
            }
        }
    }
}

// ---------------- launch ----------------
extern "C" void kernel_launch(void* const* d_in, const int* in_sizes, int n_in,
                              void* d_out, int out_size)
{
    const float* x     = (const float*)d_in[0];
    const float* noise = (const float*)d_in[1];
    const float* rw    = (const float*)d_in[2];
    const float* rb    = (const float*)d_in[3];
    const float* w1    = (const float*)d_in[4];
    const float* b1    = (const float*)d_in[5];
    const float* w2    = (const float*)d_in[6];
    const float* b2    = (const float*)d_in[7];
    float* out = (float*)d_out;

    static __nv_bfloat16 *p_W1h, *p_W1l, *p_W2h, *p_W2l, *p_Agh, *p_Agl, *p_Hh, *p_Hl;
    static bool resolved = false;
    if (!resolved) {
        cudaGetSymbolAddress((void**)&p_W1h, g_W1h);
        cudaGetSymbolAddress((void**)&p_W1l, g_W1l);
        cudaGetSymbolAddress((void**)&p_W2h, g_W2h);
        cudaGetSymbolAddress((void**)&p_W2l, g_W2l);
        cudaGetSymbolAddress((void**)&p_Agh, g_Agh);
        cudaGetSymbolAddress((void**)&p_Agl, g_Agl);
        cudaGetSymbolAddress((void**)&p_Hh, g_Hh);
        cudaGetSymbolAddress((void**)&p_Hl, g_Hl);
        cudaFuncSetAttribute(gemm_kernel,
                             cudaFuncAttributeMaxDynamicSharedMemorySize, SMEM_REQ);
        resolved = true;
    }

    // weight transpose + split (independent of routing)
    transcvt_kernel<<<dim3(DFF / 32, DIM / 32, NEXP), dim3(32, 8)>>>(w1, p_W1h, p_W1l, DIM, DFF);
    transcvt_kernel<<<dim3(DIM / 32, DFF / 32, NEXP), dim3(32, 8)>>>(w2, p_W2h, p_W2l, DFF, DIM);

    // routing
    init_kernel<<<1, 32>>>();
    router_kernel<<<TOK, 128>>>(x, noise, rw, rb);
    rank_kernel<<<NEXP, 256>>>();
    finalize_kernel<<<TOK / 256, 256>>>();
    offsets_kernel<<<1, 32>>>();
    perminit_kernel<<<(PADMAX + 255) / 256, 256>>>();
    place_kernel<<<TOK / 256, 256>>>();

    // gather + zero
    gather_kernel<<<PADMAX, 256>>>(x);
    zero_out_kernel<<<2048, 256>>>(out);

    // FFN pass 1: H = gelu(Xg @ W1^T + b1)   K=1024, N=4096
    gemm_kernel<<<dim3(DFF / 128, MAXROWTILES), 256, SMEM_REQ>>>(
        p_Agh, p_Agl, p_W1h, p_W1l, b1, nullptr, DIM, DFF, 1);

    // FFN pass 2: out = H @ W2^T + b2 (scatter)   K=4096, N=1024
    gemm_kernel<<<dim3(DIM / 128, MAXROWTILES), 256, SMEM_REQ>>>(
        p_Hh, p_Hl, p_W2h, p_W2l, b2, out, DFF, DIM, 2);
}

// round 4
// speedup vs baseline: 3.6207x; 1.4111x over previous
#include <cuda_runtime.h>
#include <cuda_fp16.h>
#include <cuda_bf16.h>
#include <math.h>
#include <stdint.h>

// ---------------- problem constants ----------------
#define TOK   16384
#define DIM   1024
#define DFF   4096
#define NEXP  8
#define CAP   3277
#define TM    128
#define PADMAX (TOK + NEXP*TM)          // 17408
#define MAXROWTILES (PADMAX/TM)         // 136
#define KC    64                         // K chunk (fp16 elems)
#define STAGE 49152                      // A 16K + Bh 16K + Bl 16K
#define NSTAGE 4
#define SMEM_REQ (NSTAGE*STAGE + 1024)

// ---------------- device scratch ----------------
__device__ unsigned char g_selmask[TOK];
__device__ unsigned char g_kept[NEXP * TOK];
__device__ signed char   g_final[TOK];
__device__ int g_cnt[NEXP];
__device__ int g_fill[NEXP];
__device__ int g_off[NEXP + 1];
__device__ int g_perm[PADMAX];
__device__ __half g_Ag[(size_t)PADMAX * DIM];        // gathered x, fp16
__device__ __half g_H [(size_t)PADMAX * DFF];        // gelu intermediate, fp16
__device__ __half g_W1h[(size_t)NEXP * DFF * DIM];   // W1^T hi
__device__ __half g_W1l[(size_t)NEXP * DFF * DIM];   // W1^T lo
__device__ __half g_W2h[(size_t)NEXP * DIM * DFF];
__device__ __half g_W2l[(size_t)NEXP * DIM * DFF];

// ---------------- helpers ----------------
__device__ __forceinline__ uint32_t smem_u32(const void* p) {
    return (uint32_t)__cvta_generic_to_shared(p);
}
#define SWZ128(o) ((o) ^ (((o) >> 3) & 0x70))

#define CP16(dst, src) \
    asm volatile("cp.async.cg.shared.global [%0], [%1], 16;" :: "r"(dst), "l"(src) : "memory")
#define CP_COMMIT() asm volatile("cp.async.commit_group;" ::: "memory")
#define CP_WAIT2()  asm volatile("cp.async.wait_group 2;" ::: "memory")

__device__ __forceinline__ void ldsm4(uint32_t& r0, uint32_t& r1, uint32_t& r2,
                                      uint32_t& r3, uint32_t addr) {
    asm volatile("ldmatrix.sync.aligned.m8n8.x4.shared.b16 {%0,%1,%2,%3}, [%4];"
                 : "=r"(r0), "=r"(r1), "=r"(r2), "=r"(r3) : "r"(addr));
}

__device__ __forceinline__ void mma16816(float* c, const uint32_t* a,
                                         uint32_t b0, uint32_t b1) {
    asm volatile(
        "mma.sync.aligned.m16n8k16.row.col.f32.f16.f16.f32 "
        "{%0,%1,%2,%3}, {%4,%5,%6,%7}, {%8,%9}, {%0,%1,%2,%3};"
        : "+f"(c[0]), "+f"(c[1]), "+f"(c[2]), "+f"(c[3])
        : "r"(a[0]), "r"(a[1]), "r"(a[2]), "r"(a[3]), "r"(b0), "r"(b1));
}

__device__ __forceinline__ float gelu_exact(float v) {
    return 0.5f * v * (1.0f + erff(v * 0.70710678118654752f));
}

// ---------------- routing kernels (unchanged, proven) ----------------
__global__ void init_kernel() {
    int i = threadIdx.x;
    if (i < NEXP) { g_cnt[i] = 0; g_fill[i] = 0; }
}

__global__ __launch_bounds__(128) void router_kernel(
    const float* __restrict__ x, const float* __restrict__ noise,
    const float* __restrict__ rw, const float* __restrict__ rb)
{
    int t = blockIdx.x;
    const float* xr = x + (size_t)t * DIM;
    float acc[NEXP];
#pragma unroll
    for (int e = 0; e < NEXP; e++) acc[e] = 0.f;
    for (int i = threadIdx.x; i < DIM; i += 128) {
        float xv = xr[i];
#pragma unroll
        for (int e = 0; e < NEXP; e++) acc[e] += xv * rw[e * DIM + i];
    }
    __shared__ float red[NEXP][128];
#pragma unroll
    for (int e = 0; e < NEXP; e++) red[e][threadIdx.x] = acc[e];
    __syncthreads();
    for (int s = 64; s > 0; s >>= 1) {
        if (threadIdx.x < s) {
#pragma unroll
            for (int e = 0; e < NEXP; e++)
                red[e][threadIdx.x] += red[e][threadIdx.x + s];
        }
        __syncthreads();
    }
    if (threadIdx.x == 0) {
        float lg[NEXP];
#pragma unroll
        for (int e = 0; e < NEXP; e++)
            lg[e] = red[e][0] + rb[e] + noise[t * NEXP + e] * 0.02f;
        int e1 = 0;
#pragma unroll
        for (int e = 1; e < NEXP; e++) if (lg[e] > lg[e1]) e1 = e;
        int e2 = -1;
#pragma unroll
        for (int e = 0; e < NEXP; e++) {
            if (e == e1) continue;
            if (e2 < 0 || lg[e] > lg[e2]) e2 = e;
        }
        g_selmask[t] = (unsigned char)((1 << e1) | (1 << e2));
    }
}

__global__ __launch_bounds__(256) void rank_kernel()
{
    int e = blockIdx.x;
    int tid = threadIdx.x;
    __shared__ int sc[256];
    __shared__ int carry;
    if (tid == 0) carry = 0;
    __syncthreads();
    for (int base = 0; base < TOK; base += 256) {
        int t = base + tid;
        int m = (g_selmask[t] >> e) & 1;
        sc[tid] = m;
        __syncthreads();
        for (int s = 1; s < 256; s <<= 1) {
            int add = (tid >= s) ? sc[tid - s] : 0;
            __syncthreads();
            sc[tid] += add;
            __syncthreads();
        }
        int incl = sc[tid];
        int rank = carry + incl - m;
        g_kept[e * TOK + t] = (unsigned char)(m && rank < CAP);
        __syncthreads();
        if (tid == 255) carry += incl;
        __syncthreads();
    }
}

__global__ __launch_bounds__(256) void finalize_kernel()
{
    int t = blockIdx.x * 256 + threadIdx.x;
    if (t >= TOK) return;
    unsigned char mask = g_selmask[t];
    int f = -1;
#pragma unroll
    for (int e = NEXP - 1; e >= 0; e--) {
        if (((mask >> e) & 1) && g_kept[e * TOK + t]) { f = e; break; }
    }
    g_final[t] = (signed char)f;
    if (f >= 0) atomicAdd(&g_cnt[f], 1);
}

__global__ void offsets_kernel()
{
    if (threadIdx.x == 0 && blockIdx.x == 0) {
        int o = 0;
        g_off[0] = 0;
        for (int e = 0; e < NEXP; e++) {
            o += ((g_cnt[e] + TM - 1) / TM) * TM;
            g_off[e + 1] = o;
        }
    }
}

__global__ __launch_bounds__(256) void perminit_kernel()
{
    int i = blockIdx.x * 256 + threadIdx.x;
    if (i < PADMAX) g_perm[i] = TOK;
}

__global__ __launch_bounds__(256) void place_kernel()
{
    int t = blockIdx.x * 256 + threadIdx.x;
    if (t >= TOK) return;
    int f = g_final[t];
    if (f >= 0) {
        int pos = g_off[f] + atomicAdd(&g_fill[f], 1);
        g_perm[pos] = t;
    }
}

__global__ __launch_bounds__(256) void zero_out_kernel(float* __restrict__ out)
{
    size_t n4 = (size_t)TOK * DIM / 4;
    float4 z = make_float4(0.f, 0.f, 0.f, 0.f);
    for (size_t i = blockIdx.x * 256 + threadIdx.x; i < n4;
         i += (size_t)gridDim.x * 256)
        reinterpret_cast<float4*>(out)[i] = z;
}

// ---------------- conversion kernels ----------------
// Transpose + fp16 split: src fp32 [E, R, C] -> dst fp16 [E, C, R] hi/lo
__global__ __launch_bounds__(256) void transcvt_kernel(
    const float* __restrict__ src, __half* __restrict__ dh,
    __half* __restrict__ dl, int R, int C)
{
    __shared__ float t[32][33];
    int e = blockIdx.z;
    const float* s = src + (size_t)e * R * C;
    int c0 = blockIdx.x * 32, r0 = blockIdx.y * 32;
    int tx = threadIdx.x, ty = threadIdx.y;
#pragma unroll
    for (int i = 0; i < 4; i++)
        t[ty + i * 8][tx] = s[(size_t)(r0 + ty + i * 8) * C + c0 + tx];
    __syncthreads();
#pragma unroll
    for (int i = 0; i < 4; i++) {
        int orow = c0 + ty + i * 8;
        int ocol = r0 + tx;
        float v = t[tx][ty + i * 8];
        __half h = __float2half(v);
        __half l = __float2half(v - __half2float(h));
        size_t di = ((size_t)e * C + orow) * R + ocol;
        dh[di] = h; dl[di] = l;
    }
}

// Gather x rows by g_perm into padded-row order, single fp16
__global__ __launch_bounds__(256) void gather_kernel(const float* __restrict__ x)
{
    int pr = blockIdx.x;
    int tok = g_perm[pr];
    int tid = threadIdx.x;
    float4 v = make_float4(0.f, 0.f, 0.f, 0.f);
    if (tok < TOK)
        v = reinterpret_cast<const float4*>(x + (size_t)tok * DIM)[tid];
    __half h[4];
    h[0] = __float2half(v.x); h[1] = __float2half(v.y);
    h[2] = __float2half(v.z); h[3] = __float2half(v.w);
    reinterpret_cast<uint2*>(g_Ag + (size_t)pr * DIM)[tid] =
        *reinterpret_cast<uint2*>(h);
}

// ---------------- HMMA GEMM (both FFN passes) ----------------
// D[128x128] = A[128 x K] * B^T, B: [N_TOT x K] row-major (k contiguous).
// 2-term fp16 split: A*Bh + A*Bl, fp32 accum. A plain fp16.
// mode 1: +b1 -> gelu -> fp16 -> g_H
// mode 2: +b2 -> scatter fp32 rows to out[token]
__global__ __launch_bounds__(256, 1) void gemm_kernel(
    const __half* __restrict__ A,
    const __half* __restrict__ Bh, const __half* __restrict__ Bl,
    const float* __restrict__ bias, float* __restrict__ out,
    int K_TOT, int N_TOT, int mode)
{
    int row0 = blockIdx.y * TM;
    if (row0 >= g_off[NEXP]) return;
    int e = 0;
#pragma unroll
    for (int i = 0; i < NEXP; i++) if (row0 >= g_off[i + 1]) e = i + 1;
    int n0 = blockIdx.x * 128;

    extern __shared__ __align__(1024) char smem_raw[];
    uint32_t sb = (smem_u32(smem_raw) + 1023) & ~1023u;

    int tid = threadIdx.x;
    int lane = tid & 31;
    int wid = tid >> 5;
    int wm = wid & 3;          // warp m position (4 x 32 rows)
    int wn = wid >> 2;         // warp n position (2 x 64 cols)
    int lrow = (lane & 7) + ((lane >> 3) & 1) * 8;
    int lkh  = (lane >> 4) * 8;

    const size_t eN = (size_t)e * N_TOT;
    const int C = K_TOT >> 6;

    // stage fill: 3072 x 16B cp.async (A + Bh + Bl, 128x64 fp16 each)
    auto fill_stage = [&](int s, int c) {
        uint32_t st = sb + s * STAGE;
        int k0 = c * KC;
#pragma unroll
        for (int j = 0; j < 4; j++) {
            int u = tid + j * 256;
            int row = u >> 3, kp = u & 7;
            uint32_t so = SWZ128(row * 128 + kp * 16);
            size_t gi = (size_t)(row0 + row) * K_TOT + k0 + kp * 8;
            CP16(st + so, (const char*)(A + gi));
            size_t gb = (eN + n0 + row) * K_TOT + k0 + kp * 8;
            CP16(st + 16384 + so, (const char*)(Bh + gb));
            CP16(st + 32768 + so, (const char*)(Bl + gb));
        }
    };

    float acc[2][8][4];
#pragma unroll
    for (int mt = 0; mt < 2; mt++)
#pragma unroll
        for (int nf = 0; nf < 8; nf++)
#pragma unroll
            for (int q = 0; q < 4; q++) acc[mt][nf][q] = 0.f;

    fill_stage(0, 0); CP_COMMIT();
    fill_stage(1, 1); CP_COMMIT();
    fill_stage(2, 2); CP_COMMIT();

    for (int c = 0; c < C; ++c) {
        int s = c & 3;
        CP_WAIT2();
        __syncthreads();
        // issue next fill first (overlaps with MMA below); stage (c+3)&3
        // was last consumed at iteration c-1 -> safe after the barrier above
        if (c + 3 < C) fill_stage((c + 3) & 3, c + 3);
        CP_COMMIT();
        uint32_t st = sb + s * STAGE;
#pragma unroll
        for (int ks = 0; ks < 4; ks++) {
            int kbyte = ks * 32 + lkh * 2;
            uint32_t a[2][4], bh[4][4], bl[4][4];
#pragma unroll
            for (int mt = 0; mt < 2; mt++) {
                uint32_t off = SWZ128((wm * 32 + mt * 16 + lrow) * 128 + kbyte);
                ldsm4(a[mt][0], a[mt][1], a[mt][2], a[mt][3], st + off);
            }
#pragma unroll
            for (int nt = 0; nt < 4; nt++) {
                uint32_t off = SWZ128((wn * 64 + nt * 16 + lrow) * 128 + kbyte);
                ldsm4(bh[nt][0], bh[nt][1], bh[nt][2], bh[nt][3], st + 16384 + off);
                ldsm4(bl[nt][0], bl[nt][1], bl[nt][2], bl[nt][3], st + 32768 + off);
            }
            // term 1: A*Bh
#pragma unroll
            for (int mt = 0; mt < 2; mt++)
#pragma unroll
                for (int nt = 0; nt < 4; nt++) {
                    mma16816(acc[mt][nt * 2],     a[mt], bh[nt][0], bh[nt][2]);
                    mma16816(acc[mt][nt * 2 + 1], a[mt], bh[nt][1], bh[nt][3]);
                }
            // term 2: A*Bl
#pragma unroll
            for (int mt = 0; mt < 2; mt++)
#pragma unroll
                for (int nt = 0; nt < 4; nt++) {
                    mma16816(acc[mt][nt * 2],     a[mt], bl[nt][0], bl[nt][2]);
                    mma16816(acc[mt][nt * 2 + 1], a[mt], bl[nt][1], bl[nt][3]);
                }
        }
        __syncthreads();
    }

    // ---- epilogue ----
    int colb = (lane & 3) * 2;
#pragma unroll
    for (int mt = 0; mt < 2; mt++) {
        int rA = row0 + wm * 32 + mt * 16 + (lane >> 2);
        int rB = rA + 8;
        int tokA = 0, tokB = 0;
        if (mode == 2) { tokA = g_perm[rA]; tokB = g_perm[rB]; }
#pragma unroll
        for (int nf = 0; nf < 8; nf++) {
            int col = n0 + wn * 64 + nf * 8 + colb;
            float bi0 = bias[(size_t)e * N_TOT + col];
            float bi1 = bias[(size_t)e * N_TOT + col + 1];
            float vA0 = acc[mt][nf][0] + bi0, vA1 = acc[mt][nf][1] + bi1;
            float vB0 = acc[mt][nf][2] + bi0, vB1 = acc[mt][nf][3] + bi1;
            if (mode == 1) {
                __half2 hA, hB;
                hA.x = __float2half(gelu_exact(vA0));
                hA.y = __float2half(gelu_exact(vA1));
                hB.x = __float2half(gelu_exact(vB0));
                hB.y = __float2half(gelu_exact(vB1));
                *reinterpret_cast<__half2*>(g_H + (size_t)rA * DFF + col) = hA;
                *reinterpret_cast<__half2*>(g_H + (size_t)rB * DFF + col) = hB;
            } else {
                if (tokA < TOK)
                    *reinterpret_cast<float2*>(out + (size_t)tokA * DIM + col) =
                        make_float2(vA0, vA1);
                if (tokB < TOK)
                    *reinterpret_cast<float2*>(out + (size_t)tokB * DIM + col) =
                        make_float2(vB0, vB1);
            }
        }
    }
}

// ---------------- launch ----------------
extern "C" void kernel_launch(void* const* d_in, const int* in_sizes, int n_in,
                              void* d_out, int out_size)
{
    const float* x     = (const float*)d_in[0];
    const float* noise = (const float*)d_in[1];
    const float* rw    = (const float*)d_in[2];
    const float* rb    = (const float*)d_in[3];
    const float* w1    = (const float*)d_in[4];
    const float* b1    = (const float*)d_in[5];
    const float* w2    = (const float*)d_in[6];
    const float* b2    = (const float*)d_in[7];
    float* out = (float*)d_out;

    static __half *p_W1h, *p_W1l, *p_W2h, *p_W2l, *p_Ag, *p_H;
    static bool resolved = false;
    if (!resolved) {
        cudaGetSymbolAddress((void**)&p_W1h, g_W1h);
        cudaGetSymbolAddress((void**)&p_W1l, g_W1l);
        cudaGetSymbolAddress((void**)&p_W2h, g_W2h);
        cudaGetSymbolAddress((void**)&p_W2l, g_W2l);
        cudaGetSymbolAddress((void**)&p_Ag, g_Ag);
        cudaGetSymbolAddress((void**)&p_H, g_H);
        cudaFuncSetAttribute(gemm_kernel,
                             cudaFuncAttributeMaxDynamicSharedMemorySize, SMEM_REQ);
        resolved = true;
    }

    // weight transpose + split (independent of routing)
    transcvt_kernel<<<dim3(DFF / 32, DIM / 32, NEXP), dim3(32, 8)>>>(w1, p_W1h, p_W1l, DIM, DFF);
    transcvt_kernel<<<dim3(DIM / 32, DFF / 32, NEXP), dim3(32, 8)>>>(w2, p_W2h, p_W2l, DFF, DIM);

    // routing
    init_kernel<<<1, 32>>>();
    router_kernel<<<TOK, 128>>>(x, noise, rw, rb);
    rank_kernel<<<NEXP, 256>>>();
    finalize_kernel<<<TOK / 256, 256>>>();
    offsets_kernel<<<1, 32>>>();
    perminit_kernel<<<(PADMAX + 255) / 256, 256>>>();
    place_kernel<<<TOK / 256, 256>>>();

    // gather + zero
    gather_kernel<<<PADMAX, 256>>>(x);
    zero_out_kernel<<<2048, 256>>>(out);

    // FFN pass 1: H = gelu(Xg @ W1^T + b1)   K=1024, N=4096
    gemm_kernel<<<dim3(DFF / 128, MAXROWTILES), 256, SMEM_REQ>>>(
        p_Ag, p_W1h, p_W1l, b1, nullptr, DIM, DFF, 1);

    // FFN pass 2: out = H @ W2^T + b2 (scatter)   K=4096, N=1024
    gemm_kernel<<<dim3(DIM / 128, MAXROWTILES), 256, SMEM_REQ>>>(
        p_H, p_W2h, p_W2l, b2, out, DFF, DIM, 2);
}

// round 5
// speedup vs baseline: 5.6023x; 1.5473x over previous
#include <cuda_runtime.h>
#include <cuda_fp16.h>
#include <math.h>
#include <stdint.h>

// ---------------- problem constants ----------------
#define TOK   16384
#define DIM   1024
#define DFF   4096
#define NEXP  8
#define CAP   3277
#define TM    128
#define PADMAX (TOK + NEXP*TM)          // 17408
#define MAXROWTILES (PADMAX/TM)         // 136
#define KC    64                         // K chunk (fp16 elems)
#define STAGE 32768                      // A 16K + B 16K
#define NSTAGE 4
#define SMEM_REQ (NSTAGE*STAGE + 1024)

// ---------------- device scratch ----------------
__device__ unsigned char g_selmask[TOK];
__device__ unsigned char g_kept[NEXP * TOK];
__device__ signed char   g_final[TOK];
__device__ int g_cnt[NEXP];
__device__ int g_fill[NEXP];
__device__ int g_off[NEXP + 1];
__device__ int g_perm[PADMAX];
__device__ __half g_Ag[(size_t)PADMAX * DIM];        // gathered x, fp16
__device__ __half g_H [(size_t)PADMAX * DFF];        // gelu intermediate, fp16
__device__ __half g_W1[(size_t)NEXP * DFF * DIM];    // W1^T fp16
__device__ __half g_W2[(size_t)NEXP * DIM * DFF];    // W2^T fp16

// ---------------- helpers ----------------
__device__ __forceinline__ uint32_t smem_u32(const void* p) {
    return (uint32_t)__cvta_generic_to_shared(p);
}
#define SWZ128(o) ((o) ^ (((o) >> 3) & 0x70))

#define CP16(dst, src) \
    asm volatile("cp.async.cg.shared.global [%0], [%1], 16;" :: "r"(dst), "l"(src) : "memory")
#define CP_COMMIT() asm volatile("cp.async.commit_group;" ::: "memory")
#define CP_WAIT2()  asm volatile("cp.async.wait_group 2;" ::: "memory")

__device__ __forceinline__ void ldsm4(uint32_t& r0, uint32_t& r1, uint32_t& r2,
                                      uint32_t& r3, uint32_t addr) {
    asm volatile("ldmatrix.sync.aligned.m8n8.x4.shared.b16 {%0,%1,%2,%3}, [%4];"
                 : "=r"(r0), "=r"(r1), "=r"(r2), "=r"(r3) : "r"(addr));
}

__device__ __forceinline__ void mma16816(float* c, const uint32_t* a,
                                         uint32_t b0, uint32_t b1) {
    asm volatile(
        "mma.sync.aligned.m16n8k16.row.col.f32.f16.f16.f32 "
        "{%0,%1,%2,%3}, {%4,%5,%6,%7}, {%8,%9}, {%0,%1,%2,%3};"
        : "+f"(c[0]), "+f"(c[1]), "+f"(c[2]), "+f"(c[3])
        : "r"(a[0]), "r"(a[1]), "r"(a[2]), "r"(a[3]), "r"(b0), "r"(b1));
}

__device__ __forceinline__ float gelu_exact(float v) {
    return 0.5f * v * (1.0f + erff(v * 0.70710678118654752f));
}

// ---------------- routing kernels (unchanged, proven) ----------------
__global__ void init_kernel() {
    int i = threadIdx.x;
    if (i < NEXP) { g_cnt[i] = 0; g_fill[i] = 0; }
}

__global__ __launch_bounds__(128) void router_kernel(
    const float* __restrict__ x, const float* __restrict__ noise,
    const float* __restrict__ rw, const float* __restrict__ rb)
{
    int t = blockIdx.x;
    const float* xr = x + (size_t)t * DIM;
    float acc[NEXP];
#pragma unroll
    for (int e = 0; e < NEXP; e++) acc[e] = 0.f;
    for (int i = threadIdx.x; i < DIM; i += 128) {
        float xv = xr[i];
#pragma unroll
        for (int e = 0; e < NEXP; e++) acc[e] += xv * rw[e * DIM + i];
    }
    __shared__ float red[NEXP][128];
#pragma unroll
    for (int e = 0; e < NEXP; e++) red[e][threadIdx.x] = acc[e];
    __syncthreads();
    for (int s = 64; s > 0; s >>= 1) {
        if (threadIdx.x < s) {
#pragma unroll
            for (int e = 0; e < NEXP; e++)
                red[e][threadIdx.x] += red[e][threadIdx.x + s];
        }
        __syncthreads();
    }
    if (threadIdx.x == 0) {
        float lg[NEXP];
#pragma unroll
        for (int e = 0; e < NEXP; e++)
            lg[e] = red[e][0] + rb[e] + noise[t * NEXP + e] * 0.02f;
        int e1 = 0;
#pragma unroll
        for (int e = 1; e < NEXP; e++) if (lg[e] > lg[e1]) e1 = e;
        int e2 = -1;
#pragma unroll
        for (int e = 0; e < NEXP; e++) {
            if (e == e1) continue;
            if (e2 < 0 || lg[e] > lg[e2]) e2 = e;
        }
        g_selmask[t] = (unsigned char)((1 << e1) | (1 << e2));
    }
}

__global__ __launch_bounds__(256) void rank_kernel()
{
    int e = blockIdx.x;
    int tid = threadIdx.x;
    __shared__ int sc[256];
    __shared__ int carry;
    if (tid == 0) carry = 0;
    __syncthreads();
    for (int base = 0; base < TOK; base += 256) {
        int t = base + tid;
        int m = (g_selmask[t] >> e) & 1;
        sc[tid] = m;
        __syncthreads();
        for (int s = 1; s < 256; s <<= 1) {
            int add = (tid >= s) ? sc[tid - s] : 0;
            __syncthreads();
            sc[tid] += add;
            __syncthreads();
        }
        int incl = sc[tid];
        int rank = carry + incl - m;
        g_kept[e * TOK + t] = (unsigned char)(m && rank < CAP);
        __syncthreads();
        if (tid == 255) carry += incl;
        __syncthreads();
    }
}

__global__ __launch_bounds__(256) void finalize_kernel()
{
    int t = blockIdx.x * 256 + threadIdx.x;
    if (t >= TOK) return;
    unsigned char mask = g_selmask[t];
    int f = -1;
#pragma unroll
    for (int e = NEXP - 1; e >= 0; e--) {
        if (((mask >> e) & 1) && g_kept[e * TOK + t]) { f = e; break; }
    }
    g_final[t] = (signed char)f;
    if (f >= 0) atomicAdd(&g_cnt[f], 1);
}

__global__ void offsets_kernel()
{
    if (threadIdx.x == 0 && blockIdx.x == 0) {
        int o = 0;
        g_off[0] = 0;
        for (int e = 0; e < NEXP; e++) {
            o += ((g_cnt[e] + TM - 1) / TM) * TM;
            g_off[e + 1] = o;
        }
    }
}

__global__ __launch_bounds__(256) void perminit_kernel()
{
    int i = blockIdx.x * 256 + threadIdx.x;
    if (i < PADMAX) g_perm[i] = TOK;
}

__global__ __launch_bounds__(256) void place_kernel()
{
    int t = blockIdx.x * 256 + threadIdx.x;
    if (t >= TOK) return;
    int f = g_final[t];
    if (f >= 0) {
        int pos = g_off[f] + atomicAdd(&g_fill[f], 1);
        g_perm[pos] = t;
    }
}

__global__ __launch_bounds__(256) void zero_out_kernel(float* __restrict__ out)
{
    size_t n4 = (size_t)TOK * DIM / 4;
    float4 z = make_float4(0.f, 0.f, 0.f, 0.f);
    for (size_t i = blockIdx.x * 256 + threadIdx.x; i < n4;
         i += (size_t)gridDim.x * 256)
        reinterpret_cast<float4*>(out)[i] = z;
}

// ---------------- conversion kernels ----------------
// Transpose + fp16 convert: src fp32 [E, R, C] -> dst fp16 [E, C, R]
__global__ __launch_bounds__(256) void transcvt_kernel(
    const float* __restrict__ src, __half* __restrict__ dh, int R, int C)
{
    __shared__ float t[32][33];
    int e = blockIdx.z;
    const float* s = src + (size_t)e * R * C;
    int c0 = blockIdx.x * 32, r0 = blockIdx.y * 32;
    int tx = threadIdx.x, ty = threadIdx.y;
#pragma unroll
    for (int i = 0; i < 4; i++)
        t[ty + i * 8][tx] = s[(size_t)(r0 + ty + i * 8) * C + c0 + tx];
    __syncthreads();
#pragma unroll
    for (int i = 0; i < 4; i++) {
        int orow = c0 + ty + i * 8;
        int ocol = r0 + tx;
        dh[((size_t)e * C + orow) * R + ocol] = __float2half(t[tx][ty + i * 8]);
    }
}

// Gather x rows by g_perm into padded-row order, fp16
__global__ __launch_bounds__(256) void gather_kernel(const float* __restrict__ x)
{
    int pr = blockIdx.x;
    int tok = g_perm[pr];
    int tid = threadIdx.x;
    float4 v = make_float4(0.f, 0.f, 0.f, 0.f);
    if (tok < TOK)
        v = reinterpret_cast<const float4*>(x + (size_t)tok * DIM)[tid];
    __half h[4];
    h[0] = __float2half(v.x); h[1] = __float2half(v.y);
    h[2] = __float2half(v.z); h[3] = __float2half(v.w);
    reinterpret_cast<uint2*>(g_Ag + (size_t)pr * DIM)[tid] =
        *reinterpret_cast<uint2*>(h);
}

// ---------------- HMMA GEMM (both FFN passes) ----------------
// D[128x128] = A[128 x K] * B^T, B: [N_TOT x K] row-major (k contiguous).
// single fp16 term, fp32 accum.
// mode 1: +b1 -> gelu -> fp16 -> g_H
// mode 2: +b2 -> scatter fp32 rows to out[token]
__global__ __launch_bounds__(256, 1) void gemm_kernel(
    const __half* __restrict__ A, const __half* __restrict__ B,
    const float* __restrict__ bias, float* __restrict__ out,
    int K_TOT, int N_TOT, int mode)
{
    int row0 = blockIdx.y * TM;
    if (row0 >= g_off[NEXP]) return;
    int e = 0;
#pragma unroll
    for (int i = 0; i < NEXP; i++) if (row0 >= g_off[i + 1]) e = i + 1;
    int n0 = blockIdx.x * 128;

    extern __shared__ __align__(1024) char smem_raw[];
    uint32_t sb = (smem_u32(smem_raw) + 1023) & ~1023u;

    int tid = threadIdx.x;
    int lane = tid & 31;
    int wid = tid >> 5;
    int wm = wid & 3;          // warp m position (4 x 32 rows)
    int wn = wid >> 2;         // warp n position (2 x 64 cols)
    int lrow = (lane & 7) + ((lane >> 3) & 1) * 8;
    int lkh  = (lane >> 4) * 8;

    const size_t eN = (size_t)e * N_TOT;
    const int C = K_TOT >> 6;

    // stage fill: 2048 x 16B cp.async (A + B, 128x64 fp16 each)
    auto fill_stage = [&](int s, int c) {
        uint32_t st = sb + s * STAGE;
        int k0 = c * KC;
#pragma unroll
        for (int j = 0; j < 4; j++) {
            int u = tid + j * 256;
            int row = u >> 3, kp = u & 7;
            uint32_t so = SWZ128(row * 128 + kp * 16);
            size_t gi = (size_t)(row0 + row) * K_TOT + k0 + kp * 8;
            CP16(st + so, (const char*)(A + gi));
            size_t gb = (eN + n0 + row) * K_TOT + k0 + kp * 8;
            CP16(st + 16384 + so, (const char*)(B + gb));
        }
    };

    float acc[2][8][4];
#pragma unroll
    for (int mt = 0; mt < 2; mt++)
#pragma unroll
        for (int nf = 0; nf < 8; nf++)
#pragma unroll
            for (int q = 0; q < 4; q++) acc[mt][nf][q] = 0.f;

    fill_stage(0, 0); CP_COMMIT();
    fill_stage(1, 1); CP_COMMIT();
    fill_stage(2, 2); CP_COMMIT();

    for (int c = 0; c < C; ++c) {
        int s = c & 3;
        CP_WAIT2();
        __syncthreads();
        // issue next fill first (overlaps with MMA below); stage (c+3)&3
        // was last consumed at iteration c-1 -> safe after the barrier above
        if (c + 3 < C) fill_stage((c + 3) & 3, c + 3);
        CP_COMMIT();
        uint32_t st = sb + s * STAGE;
#pragma unroll
        for (int ks = 0; ks < 4; ks++) {
            int kbyte = ks * 32 + lkh * 2;
            uint32_t a[2][4], bh[4][4];
#pragma unroll
            for (int mt = 0; mt < 2; mt++) {
                uint32_t off = SWZ128((wm * 32 + mt * 16 + lrow) * 128 + kbyte);
                ldsm4(a[mt][0], a[mt][1], a[mt][2], a[mt][3], st + off);
            }
#pragma unroll
            for (int nt = 0; nt < 4; nt++) {
                uint32_t off = SWZ128((wn * 64 + nt * 16 + lrow) * 128 + kbyte);
                ldsm4(bh[nt][0], bh[nt][1], bh[nt][2], bh[nt][3], st + 16384 + off);
            }
#pragma unroll
            for (int mt = 0; mt < 2; mt++)
#pragma unroll
                for (int nt = 0; nt < 4; nt++) {
                    mma16816(acc[mt][nt * 2],     a[mt], bh[nt][0], bh[nt][2]);
                    mma16816(acc[mt][nt * 2 + 1], a[mt], bh[nt][1], bh[nt][3]);
                }
        }
        __syncthreads();
    }

    // ---- epilogue ----
    int colb = (lane & 3) * 2;
#pragma unroll
    for (int mt = 0; mt < 2; mt++) {
        int rA = row0 + wm * 32 + mt * 16 + (lane >> 2);
        int rB = rA + 8;
        int tokA = 0, tokB = 0;
        if (mode == 2) { tokA = g_perm[rA]; tokB = g_perm[rB]; }
#pragma unroll
        for (int nf = 0; nf < 8; nf++) {
            int col = n0 + wn * 64 + nf * 8 + colb;
            float bi0 = bias[(size_t)e * N_TOT + col];
            float bi1 = bias[(size_t)e * N_TOT + col + 1];
            float vA0 = acc[mt][nf][0] + bi0, vA1 = acc[mt][nf][1] + bi1;
            float vB0 = acc[mt][nf][2] + bi0, vB1 = acc[mt][nf][3] + bi1;
            if (mode == 1) {
                __half2 hA, hB;
                hA.x = __float2half(gelu_exact(vA0));
                hA.y = __float2half(gelu_exact(vA1));
                hB.x = __float2half(gelu_exact(vB0));
                hB.y = __float2half(gelu_exact(vB1));
                *reinterpret_cast<__half2*>(g_H + (size_t)rA * DFF + col) = hA;
                *reinterpret_cast<__half2*>(g_H + (size_t)rB * DFF + col) = hB;
            } else {
                if (tokA < TOK)
                    *reinterpret_cast<float2*>(out + (size_t)tokA * DIM + col) =
                        make_float2(vA0, vA1);
                if (tokB < TOK)
                    *reinterpret_cast<float2*>(out + (size_t)tokB * DIM + col) =
                        make_float2(vB0, vB1);
            }
        }
    }
}

// ---------------- launch ----------------
extern "C" void kernel_launch(void* const* d_in, const int* in_sizes, int n_in,
                              void* d_out, int out_size)
{
    const float* x     = (const float*)d_in[0];
    const float* noise = (const float*)d_in[1];
    const float* rw    = (const float*)d_in[2];
    const float* rb    = (const float*)d_in[3];
    const float* w1    = (const float*)d_in[4];
    const float* b1    = (const float*)d_in[5];
    const float* w2    = (const float*)d_in[6];
    const float* b2    = (const float*)d_in[7];
    float* out = (float*)d_out;

    static __half *p_W1, *p_W2, *p_Ag, *p_H;
    static bool resolved = false;
    if (!resolved) {
        cudaGetSymbolAddress((void**)&p_W1, g_W1);
        cudaGetSymbolAddress((void**)&p_W2, g_W2);
        cudaGetSymbolAddress((void**)&p_Ag, g_Ag);
        cudaGetSymbolAddress((void**)&p_H, g_H);
        cudaFuncSetAttribute(gemm_kernel,
                             cudaFuncAttributeMaxDynamicSharedMemorySize, SMEM_REQ);
        resolved = true;
    }

    // weight transpose + convert (independent of routing)
    transcvt_kernel<<<dim3(DFF / 32, DIM / 32, NEXP), dim3(32, 8)>>>(w1, p_W1, DIM, DFF);
    transcvt_kernel<<<dim3(DIM / 32, DFF / 32, NEXP), dim3(32, 8)>>>(w2, p_W2, DFF, DIM);

    // routing
    init_kernel<<<1, 32>>>();
    router_kernel<<<TOK, 128>>>(x, noise, rw, rb);
    rank_kernel<<<NEXP, 256>>>();
    finalize_kernel<<<TOK / 256, 256>>>();
    offsets_kernel<<<1, 32>>>();
    perminit_kernel<<<(PADMAX + 255) / 256, 256>>>();
    place_kernel<<<TOK / 256, 256>>>();

    // gather + zero
    gather_kernel<<<PADMAX, 256>>>(x);
    zero_out_kernel<<<2048, 256>>>(out);

    // FFN pass 1: H = gelu(Xg @ W1^T + b1)   K=1024, N=4096
    gemm_kernel<<<dim3(DFF / 128, MAXROWTILES), 256, SMEM_REQ>>>(
        p_Ag, p_W1, b1, nullptr, DIM, DFF, 1);

    // FFN pass 2: out = H @ W2^T + b2 (scatter)   K=4096, N=1024
    gemm_kernel<<<dim3(DIM / 128, MAXROWTILES), 256, SMEM_REQ>>>(
        p_H, p_W2, b2, out, DFF, DIM, 2);
}

// round 8
// speedup vs baseline: 6.2183x; 1.1099x over previous
#include <cuda_runtime.h>
#include <cuda_fp16.h>
#include <math.h>
#include <stdint.h>

// ---------------- problem constants ----------------
#define TOK   16384
#define DIM   1024
#define DFF   4096
#define NEXP  8
#define CAP   3277
#define TM    128
#define PADMAX (TOK + NEXP*TM)          // 17408
#define MAXROWTILES (PADMAX/TM)         // 136
#define KC    64                         // K chunk (fp16 elems)
#define STAGE 32768                      // A 16K + B 16K
#define NSTAGE 3
#define SMEM_REQ (NSTAGE*STAGE + 1024)   // 99328; x2 CTAs = 198656 <= 227KB

// ---------------- device scratch ----------------
__device__ unsigned char g_selmask[TOK];
__device__ unsigned char g_kept[NEXP * TOK];
__device__ signed char   g_final[TOK];
__device__ int g_cnt[NEXP];
__device__ int g_fill[NEXP];
__device__ int g_off[NEXP + 1];
__device__ int g_perm[PADMAX];
__device__ __half g_Ag[(size_t)PADMAX * DIM];        // gathered x, fp16
__device__ __half g_H [(size_t)PADMAX * DFF];        // gelu intermediate, fp16
__device__ __half g_W1[(size_t)NEXP * DFF * DIM];    // W1^T fp16
__device__ __half g_W2[(size_t)NEXP * DIM * DFF];    // W2^T fp16

// ---------------- helpers ----------------
__device__ __forceinline__ uint32_t smem_u32(const void* p) {
    return (uint32_t)__cvta_generic_to_shared(p);
}
#define SWZ128(o) ((o) ^ (((o) >> 3) & 0x70))

#define CP16(dst, src) \
    asm volatile("cp.async.cg.shared.global [%0], [%1], 16;" :: "r"(dst), "l"(src) : "memory")
#define CP_COMMIT() asm volatile("cp.async.commit_group;" ::: "memory")
#define CP_WAIT1()  asm volatile("cp.async.wait_group 1;" ::: "memory")

__device__ __forceinline__ void ldsm4(uint32_t& r0, uint32_t& r1, uint32_t& r2,
                                      uint32_t& r3, uint32_t addr) {
    asm volatile("ldmatrix.sync.aligned.m8n8.x4.shared.b16 {%0,%1,%2,%3}, [%4];"
                 : "=r"(r0), "=r"(r1), "=r"(r2), "=r"(r3) : "r"(addr));
}

__device__ __forceinline__ void mma16816(float* c, const uint32_t* a,
                                         uint32_t b0, uint32_t b1) {
    asm volatile(
        "mma.sync.aligned.m16n8k16.row.col.f32.f16.f16.f32 "
        "{%0,%1,%2,%3}, {%4,%5,%6,%7}, {%8,%9}, {%0,%1,%2,%3};"
        : "+f"(c[0]), "+f"(c[1]), "+f"(c[2]), "+f"(c[3])
        : "r"(a[0]), "r"(a[1]), "r"(a[2]), "r"(a[3]), "r"(b0), "r"(b1));
}

__device__ __forceinline__ float gelu_exact(float v) {
    return 0.5f * v * (1.0f + erff(v * 0.70710678118654752f));
}

// ---------------- routing kernels ----------------
__global__ void init_kernel() {
    int i = threadIdx.x;
    if (i < NEXP) { g_cnt[i] = 0; g_fill[i] = 0; }
}

// router: float4-vectorized logits + noise, top-2
__global__ __launch_bounds__(128) void router_kernel(
    const float* __restrict__ x, const float* __restrict__ noise,
    const float* __restrict__ rw, const float* __restrict__ rb)
{
    int t = blockIdx.x;
    const float4* xr4 = reinterpret_cast<const float4*>(x + (size_t)t * DIM);
    const float4* rw4 = reinterpret_cast<const float4*>(rw);
    float acc[NEXP];
#pragma unroll
    for (int e = 0; e < NEXP; e++) acc[e] = 0.f;
#pragma unroll
    for (int it = 0; it < 2; it++) {
        int idx = threadIdx.x + it * 128;      // DIM/4 = 256
        float4 xv = xr4[idx];
#pragma unroll
        for (int e = 0; e < NEXP; e++) {
            float4 wv = rw4[e * 256 + idx];
            acc[e] += xv.x * wv.x + xv.y * wv.y + xv.z * wv.z + xv.w * wv.w;
        }
    }
    __shared__ float red[NEXP][128];
#pragma unroll
    for (int e = 0; e < NEXP; e++) red[e][threadIdx.x] = acc[e];
    __syncthreads();
    for (int s = 64; s > 0; s >>= 1) {
        if (threadIdx.x < s) {
#pragma unroll
            for (int e = 0; e < NEXP; e++)
                red[e][threadIdx.x] += red[e][threadIdx.x + s];
        }
        __syncthreads();
    }
    if (threadIdx.x == 0) {
        float lg[NEXP];
#pragma unroll
        for (int e = 0; e < NEXP; e++)
            lg[e] = red[e][0] + rb[e] + noise[t * NEXP + e] * 0.02f;
        int e1 = 0;
#pragma unroll
        for (int e = 1; e < NEXP; e++) if (lg[e] > lg[e1]) e1 = e;
        int e2 = -1;
#pragma unroll
        for (int e = 0; e < NEXP; e++) {
            if (e == e1) continue;
            if (e2 < 0 || lg[e] > lg[e2]) e2 = e;
        }
        g_selmask[t] = (unsigned char)((1 << e1) | (1 << e2));
    }
}

// per-expert capacity filter via ballot words + block scan (8 blocks x 512 thr)
__global__ __launch_bounds__(512) void rank_kernel()
{
    int e = blockIdx.x;
    int tid = threadIdx.x;                 // 0..511, each owns 32 tokens
    union { uint4 v[2]; unsigned char b[32]; } u;
    u.v[0] = reinterpret_cast<const uint4*>(g_selmask)[tid * 2];
    u.v[1] = reinterpret_cast<const uint4*>(g_selmask)[tid * 2 + 1];
    uint32_t mask = 0;
#pragma unroll
    for (int j = 0; j < 32; j++)
        mask |= (uint32_t)((u.b[j] >> e) & 1) << j;
    int cnt = __popc(mask);
    __shared__ int sc[512];
    sc[tid] = cnt;
    __syncthreads();
    for (int s = 1; s < 512; s <<= 1) {
        int add = (tid >= s) ? sc[tid - s] : 0;
        __syncthreads();
        sc[tid] += add;
        __syncthreads();
    }
    int base = sc[tid] - cnt;              // exclusive prefix
    union { uint4 v[2]; unsigned char b[32]; } o;
#pragma unroll
    for (int j = 0; j < 32; j++) {
        int m = (mask >> j) & 1;
        int rank = base + __popc(mask & ((1u << j) - 1u));
        o.b[j] = (unsigned char)(m && rank < CAP);
    }
    reinterpret_cast<uint4*>(g_kept + (size_t)e * TOK)[tid * 2]     = o.v[0];
    reinterpret_cast<uint4*>(g_kept + (size_t)e * TOK)[tid * 2 + 1] = o.v[1];
}

__global__ __launch_bounds__(256) void finalize_kernel()
{
    __shared__ int loc[NEXP];
    if (threadIdx.x < NEXP) loc[threadIdx.x] = 0;
    __syncthreads();
    int t = blockIdx.x * 256 + threadIdx.x;
    unsigned char mask = g_selmask[t];
    int f = -1;
#pragma unroll
    for (int e = NEXP - 1; e >= 0; e--) {
        if (((mask >> e) & 1) && g_kept[e * TOK + t]) { f = e; break; }
    }
    g_final[t] = (signed char)f;
    if (f >= 0) atomicAdd(&loc[f], 1);
    __syncthreads();
    if (threadIdx.x < NEXP && loc[threadIdx.x] > 0)
        atomicAdd(&g_cnt[threadIdx.x], loc[threadIdx.x]);
}

__global__ void offsets_kernel()
{
    if (threadIdx.x == 0 && blockIdx.x == 0) {
        int o = 0;
        g_off[0] = 0;
        for (int e = 0; e < NEXP; e++) {
            o += ((g_cnt[e] + TM - 1) / TM) * TM;
            g_off[e + 1] = o;
        }
    }
}

__global__ __launch_bounds__(256) void perminit_kernel()
{
    int i = blockIdx.x * 256 + threadIdx.x;
    if (i < PADMAX) g_perm[i] = TOK;
}

__global__ __launch_bounds__(256) void place_kernel()
{
    int t = blockIdx.x * 256 + threadIdx.x;
    if (t >= TOK) return;
    int f = g_final[t];
    if (f >= 0) {
        int pos = g_off[f] + atomicAdd(&g_fill[f], 1);
        g_perm[pos] = t;
    }
}

// zero only dropped-token rows (everything else is written by FFN pass 2)
__global__ __launch_bounds__(256) void zero_dropped_kernel(float* __restrict__ out)
{
    __shared__ int list[256];
    __shared__ int cnt;
    if (threadIdx.x == 0) cnt = 0;
    __syncthreads();
    int t = blockIdx.x * 256 + threadIdx.x;
    if (g_final[t] < 0) { int p = atomicAdd(&cnt, 1); list[p] = t; }
    __syncthreads();
    float4 z = make_float4(0.f, 0.f, 0.f, 0.f);
    for (int i = 0; i < cnt; i++) {
        size_t row = (size_t)list[i] * DIM;
        reinterpret_cast<float4*>(out + row)[threadIdx.x] = z;  // 256*4 = 1024
    }
}

// ---------------- conversion kernels ----------------
// Transpose + fp16 convert: src fp32 [E, R, C] -> dst fp16 [E, C, R]
__global__ __launch_bounds__(256) void transcvt_kernel(
    const float* __restrict__ src, __half* __restrict__ dh, int R, int C)
{
    __shared__ float t[32][33];
    int e = blockIdx.z;
    const float* s = src + (size_t)e * R * C;
    int c0 = blockIdx.x * 32, r0 = blockIdx.y * 32;
    int tx = threadIdx.x, ty = threadIdx.y;
#pragma unroll
    for (int i = 0; i < 4; i++)
        t[ty + i * 8][tx] = s[(size_t)(r0 + ty + i * 8) * C + c0 + tx];
    __syncthreads();
#pragma unroll
    for (int i = 0; i < 4; i++) {
        int orow = c0 + ty + i * 8;
        int ocol = r0 + tx;
        dh[((size_t)e * C + orow) * R + ocol] = __float2half(t[tx][ty + i * 8]);
    }
}

// Gather x rows by g_perm into padded-row order, fp16
__global__ __launch_bounds__(256) void gather_kernel(const float* __restrict__ x)
{
    int pr = blockIdx.x;
    int tok = g_perm[pr];
    int tid = threadIdx.x;
    float4 v = make_float4(0.f, 0.f, 0.f, 0.f);
    if (tok < TOK)
        v = reinterpret_cast<const float4*>(x + (size_t)tok * DIM)[tid];
    __half h[4];
    h[0] = __float2half(v.x); h[1] = __float2half(v.y);
    h[2] = __float2half(v.z); h[3] = __float2half(v.w);
    reinterpret_cast<uint2*>(g_Ag + (size_t)pr * DIM)[tid] =
        *reinterpret_cast<uint2*>(h);
}

// ---------------- HMMA GEMM (both FFN passes) ----------------
// D[128x128] = A[128 x K] * B^T, B: [N_TOT x K] row-major (k contiguous).
// single fp16 term, fp32 accum. 3-stage cp.async pipeline, 2 CTAs/SM.
// mode 1: +b1 -> gelu -> fp16 -> g_H
// mode 2: +b2 -> scatter fp32 rows to out[token]
__global__ __launch_bounds__(256, 2) void gemm_kernel(
    const __half* __restrict__ A, const __half* __restrict__ B,
    const float* __restrict__ bias, float* __restrict__ out,
    int K_TOT, int N_TOT, int mode)
{
    int row0 = blockIdx.y * TM;
    if (row0 >= g_off[NEXP]) return;
    int e = 0;
#pragma unroll
    for (int i = 0; i < NEXP; i++) if (row0 >= g_off[i + 1]) e = i + 1;
    int n0 = blockIdx.x * 128;

    extern __shared__ __align__(1024) char smem_raw[];
    uint32_t sb = (smem_u32(smem_raw) + 1023) & ~1023u;

    int tid = threadIdx.x;
    int lane = tid & 31;
    int wid = tid >> 5;
    int wm = wid & 3;          // warp m position (4 x 32 rows)
    int wn = wid >> 2;         // warp n position (2 x 64 cols)
    int lrow = (lane & 7) + ((lane >> 3) & 1) * 8;
    int lkh  = (lane >> 4) * 8;

    const size_t eN = (size_t)e * N_TOT;
    const int C = K_TOT >> 6;

    // stage fill: 2048 x 16B cp.async (A + B, 128x64 fp16 each)
    auto fill_stage = [&](int s, int c) {
        uint32_t st = sb + s * STAGE;
        int k0 = c * KC;
#pragma unroll
        for (int j = 0; j < 4; j++) {
            int u = tid + j * 256;
            int row = u >> 3, kp = u & 7;
            uint32_t so = SWZ128(row * 128 + kp * 16);
            size_t gi = (size_t)(row0 + row) * K_TOT + k0 + kp * 8;
            CP16(st + so, (const char*)(A + gi));
            size_t gb = (eN + n0 + row) * K_TOT + k0 + kp * 8;
            CP16(st + 16384 + so, (const char*)(B + gb));
        }
    };

    float acc[2][8][4];
#pragma unroll
    for (int mt = 0; mt < 2; mt++)
#pragma unroll
        for (int nf = 0; nf < 8; nf++)
#pragma unroll
            for (int q = 0; q < 4; q++) acc[mt][nf][q] = 0.f;

    fill_stage(0, 0); CP_COMMIT();
    fill_stage(1, 1); CP_COMMIT();

    for (int c = 0; c < C; ++c) {
        int s = c % 3;
        CP_WAIT1();
        __syncthreads();
        // refill stage (c+2)%3 == (c-1)%3, consumed at iter c-1 (safe: end sync)
        if (c + 2 < C) fill_stage((c + 2) % 3, c + 2);
        CP_COMMIT();
        uint32_t st = sb + s * STAGE;
#pragma unroll
        for (int ks = 0; ks < 4; ks++) {
            int kbyte = ks * 32 + lkh * 2;
            uint32_t a[2][4], bh[4][4];
#pragma unroll
            for (int mt = 0; mt < 2; mt++) {
                uint32_t off = SWZ128((wm * 32 + mt * 16 + lrow) * 128 + kbyte);
                ldsm4(a[mt][0], a[mt][1], a[mt][2], a[mt][3], st + off);
            }
#pragma unroll
            for (int nt = 0; nt < 4; nt++) {
                uint32_t off = SWZ128((wn * 64 + nt * 16 + lrow) * 128 + kbyte);
                ldsm4(bh[nt][0], bh[nt][1], bh[nt][2], bh[nt][3], st + 16384 + off);
            }
#pragma unroll
            for (int mt = 0; mt < 2; mt++)
#pragma unroll
                for (int nt = 0; nt < 4; nt++) {
                    mma16816(acc[mt][nt * 2],     a[mt], bh[nt][0], bh[nt][2]);
                    mma16816(acc[mt][nt * 2 + 1], a[mt], bh[nt][1], bh[nt][3]);
                }
        }
        __syncthreads();
    }

    // ---- epilogue ----
    int colb = (lane & 3) * 2;
#pragma unroll
    for (int mt = 0; mt < 2; mt++) {
        int rA = row0 + wm * 32 + mt * 16 + (lane >> 2);
        int rB = rA + 8;
        int tokA = 0, tokB = 0;
        if (mode == 2) { tokA = g_perm[rA]; tokB = g_perm[rB]; }
#pragma unroll
        for (int nf = 0; nf < 8; nf++) {
            int col = n0 + wn * 64 + nf * 8 + colb;
            float bi0 = bias[(size_t)e * N_TOT + col];
            float bi1 = bias[(size_t)e * N_TOT + col + 1];
            float vA0 = acc[mt][nf][0] + bi0, vA1 = acc[mt][nf][1] + bi1;
            float vB0 = acc[mt][nf][2] + bi0, vB1 = acc[mt][nf][3] + bi1;
            if (mode == 1) {
                __half2 hA, hB;
                hA.x = __float2half(gelu_exact(vA0));
                hA.y = __float2half(gelu_exact(vA1));
                hB.x = __float2half(gelu_exact(vB0));
                hB.y = __float2half(gelu_exact(vB1));
                *reinterpret_cast<__half2*>(g_H + (size_t)rA * DFF + col) = hA;
                *reinterpret_cast<__half2*>(g_H + (size_t)rB * DFF + col) = hB;
            } else {
                if (tokA < TOK)
                    *reinterpret_cast<float2*>(out + (size_t)tokA * DIM + col) =
                        make_float2(vA0, vA1);
                if (tokB < TOK)
                    *reinterpret_cast<float2*>(out + (size_t)tokB * DIM + col) =
                        make_float2(vB0, vB1);
            }
        }
    }
}

// ---------------- launch (single stream; no events — graph-capture safe) ----
extern "C" void kernel_launch(void* const* d_in, const int* in_sizes, int n_in,
                              void* d_out, int out_size)
{
    const float* x     = (const float*)d_in[0];
    const float* noise = (const float*)d_in[1];
    const float* rw    = (const float*)d_in[2];
    const float* rb    = (const float*)d_in[3];
    const float* w1    = (const float*)d_in[4];
    const float* b1    = (const float*)d_in[5];
    const float* w2    = (const float*)d_in[6];
    const float* b2    = (const float*)d_in[7];
    float* out = (float*)d_out;

    static __half *p_W1, *p_W2, *p_Ag, *p_H;
    static bool resolved = false;
    if (!resolved) {
        cudaGetSymbolAddress((void**)&p_W1, g_W1);
        cudaGetSymbolAddress((void**)&p_W2, g_W2);
        cudaGetSymbolAddress((void**)&p_Ag, g_Ag);
        cudaGetSymbolAddress((void**)&p_H, g_H);
        cudaFuncSetAttribute(gemm_kernel,
                             cudaFuncAttributeMaxDynamicSharedMemorySize, SMEM_REQ);
        resolved = true;
    }

    // weight transpose + convert
    transcvt_kernel<<<dim3(DFF / 32, DIM / 32, NEXP), dim3(32, 8)>>>(w1, p_W1, DIM, DFF);
    transcvt_kernel<<<dim3(DIM / 32, DFF / 32, NEXP), dim3(32, 8)>>>(w2, p_W2, DFF, DIM);

    // routing chain
    init_kernel<<<1, 32>>>();
    router_kernel<<<TOK, 128>>>(x, noise, rw, rb);
    rank_kernel<<<NEXP, 512>>>();
    finalize_kernel<<<TOK / 256, 256>>>();
    offsets_kernel<<<1, 32>>>();
    perminit_kernel<<<(PADMAX + 255) / 256, 256>>>();
    place_kernel<<<TOK / 256, 256>>>();
    gather_kernel<<<PADMAX, 256>>>(x);
    zero_dropped_kernel<<<TOK / 256, 256>>>(out);

    // FFN pass 1: H = gelu(Xg @ W1^T + b1)   K=1024, N=4096
    gemm_kernel<<<dim3(DFF / 128, MAXROWTILES), 256, SMEM_REQ>>>(
        p_Ag, p_W1, b1, nullptr, DIM, DFF, 1);

    // FFN pass 2: out = H @ W2^T + b2 (scatter)   K=4096, N=1024
    gemm_kernel<<<dim3(DIM / 128, MAXROWTILES), 256, SMEM_REQ>>>(
        p_H, p_W2, b2, out, DFF, DIM, 2);
}